// round 17
// baseline (speedup 1.0000x reference)
#include <cuda_runtime.h>

#define SIZE 512
#define NS 256
#define NT 128
#define KST4 68                // per-warp keep stride in float4 (136 float2 >= 128+4)
#define KSCALE 369.3298503f    // 256 * log2(e)

__device__ __forceinline__ float fsqrt_approx(float x) {
    float r; asm("sqrt.approx.f32 %0, %1;" : "=f"(r) : "f"(x)); return r;
}
__device__ __forceinline__ float fexp2_approx(float x) {
    float r; asm("ex2.approx.f32 %0, %1;" : "=f"(r) : "f"(x)); return r;
}
__device__ __forceinline__ float flog2_approx(float x) {
    float r; asm("lg2.approx.f32 %0, %1;" : "=f"(r) : "f"(x)); return r;
}
__device__ __forceinline__ float frcp_approx(float x) {
    float r; asm("rcp.approx.f32 %0, %1;" : "=f"(r) : "f"(x)); return r;
}

// ---- fused kernel: 2 warp-PAIRS per CTA; each pair owns one 8x8 tile and
//      splits the kept samples by parity between its two warps ----
__global__ __launch_bounds__(NT)
void glyph_kernel(const float* __restrict__ cp, float* __restrict__ out)
{
    __shared__ float4 samp[NS / 2];          // 256 K-scaled samples
    __shared__ float4 keepbuf[4 * KST4];     // private half-list per warp
    __shared__ float  partial[4][64];        // per-warp per-pixel partial sums

    const int tid  = threadIdx.x;
    const int lane = tid & 31;
    const int w    = tid >> 5;
    const int pair = w >> 1;                 // 0 or 1
    const int h    = w & 1;                  // half index within pair

    // ---- per-CTA K-scaled Bezier samples: thread t computes samples 2t, 2t+1 ----
    {
        const float4* cp4 = (const float4*)cp;
        const int stroke = tid >> 4;
        const float4 a = cp4[2 * stroke];
        const float4 b = cp4[2 * stroke + 1];
        const float q0x = __saturatef(a.x), q0y = __saturatef(a.y);
        const float q1x = __saturatef(a.z), q1y = __saturatef(a.w);
        const float q2x = __saturatef(b.x), q2y = __saturatef(b.y);
        const float q3x = __saturatef(b.z), q3y = __saturatef(b.w);
        const int j = (2 * tid) & 31;
        float4 o;
        {
            const float t  = (float)j * (1.0f / 31.0f);
            const float mt = 1.0f - t;
            const float w0 = mt * mt * mt, w1 = 3.0f * mt * mt * t;
            const float w2 = 3.0f * mt * t * t, w3 = t * t * t;
            o.x = (w0 * q0x + w1 * q1x + w2 * q2x + w3 * q3x) * KSCALE;
            o.y = (w0 * q0y + w1 * q1y + w2 * q2y + w3 * q3y) * KSCALE;
        }
        {
            const float t  = (float)(j + 1) * (1.0f / 31.0f);
            const float mt = 1.0f - t;
            const float w0 = mt * mt * mt, w1 = 3.0f * mt * mt * t;
            const float w2 = 3.0f * mt * t * t, w3 = t * t * t;
            o.z = (w0 * q0x + w1 * q1x + w2 * q2x + w3 * q3x) * KSCALE;
            o.w = (w0 * q0y + w1 * q1y + w2 * q2y + w3 * q3y) * KSCALE;
        }
        samp[tid] = o;
    }
    __syncthreads();

    const int tile = blockIdx.x * 2 + pair;  // 0..4095
    const int x0 = (tile & 63) * 8;          // 64 x 64 tiles of 8x8 px
    const int y0 = (tile >> 6) * 8;

    const float inv = 1.0f / 511.0f;
    const float cxs = ((float)x0 + 3.5f) * inv * KSCALE;
    const float cys = ((float)y0 + 3.5f) * inv * KSCALE;
    const float R  = 0.0096875f + 1e-4f;     // 0.5*sqrt(7^2+7^2)/511

    // ---- full prologue in BOTH warps of the pair (same dcmin -> same branch) ----
    float2 s[8];
    float  dc2[8];
    float  m = 1e30f;
    #pragma unroll
    for (int j = 0; j < 4; j++) {
        const float4 v = samp[j * 32 + lane];
        s[2 * j]     = make_float2(v.x, v.y);
        s[2 * j + 1] = make_float2(v.z, v.w);
        float ax = cxs - v.x, ay = cys - v.y;
        dc2[2 * j] = fmaf(ax, ax, ay * ay);
        ax = cxs - v.z; ay = cys - v.w;
        dc2[2 * j + 1] = fmaf(ax, ax, ay * ay);
        m = fminf(m, fminf(dc2[2 * j], dc2[2 * j + 1]));
    }
    const float dcmin_s =
        sqrtf(__int_as_float(__reduce_min_sync(0xffffffffu, __float_as_int(m))));

    // this warp finalizes pixel q = 32h + lane of the 64-pixel tile
    const int q  = 32 * h + lane;
    const int fx = x0 + (q & 7);
    const int fy = y0 + ((q >> 3) & 3) + ((q >> 5) << 2);
    const int fp = fy * SIZE + fx;

    // ---- tile skip (no barrier on this path) ----
    if (dcmin_s > 0.1154f * KSCALE) {
        out[fp] = 1.0f;
        return;
    }

    // ---- parity-half compaction: warp h keeps samples with (index & 1) == h ----
    const float thr  = dcmin_s + (2.0f * R + 0.055f) * KSCALE;
    const float thr2 = thr * thr;
    float2* kp = (float2*)(keepbuf + w * KST4);
    const unsigned lt = (1u << lane) - 1u;
    int c = 0;
    #pragma unroll
    for (int jj = 0; jj < 4; jj++) {
        const int j = 2 * jj + h;            // own-parity samples only
        const bool k = (dc2[j] <= thr2);
        const unsigned msk = __ballot_sync(0xffffffffu, k);
        if (k) kp[c + __popc(msk & lt)] = s[j];
        c += __popc(msk);
    }
    if (lane < 4) kp[c + lane] = make_float2(cxs + 1000.0f, cys);  // ex2(-1000)=0
    __syncwarp();
    const int nIt = ((c + 3) & ~3) >> 1;

    // ---- half-list soft-min over 2 pixels per lane (as R15) ----
    const int px = x0 + (lane & 7);
    const int py = y0 + (lane >> 3);
    const float gxs  = (float)px * inv * KSCALE;
    const float gy1s = (float)py * inv * KSCALE;
    const float DYS  = 4.0f * inv * KSCALE;
    const float4* kp4 = (const float4*)kp;
    float a1A = 0.0f, a1B = 0.0f, a2A = 0.0f, a2B = 0.0f;
    #pragma unroll 4
    for (int i = 0; i < nIt; i++) {
        const float4 qv = kp4[i];
        float ax  = gxs - qv.x;
        float axx = ax * ax;
        float ay  = gy1s - qv.y;
        float ay2 = ay + DYS;
        const float dA1 = fsqrt_approx(fmaf(ay,  ay,  axx));
        const float dA2 = fsqrt_approx(fmaf(ay2, ay2, axx));
        float bx  = gxs - qv.z;
        float bxx = bx * bx;
        float by  = gy1s - qv.w;
        float by2 = by + DYS;
        const float dB1 = fsqrt_approx(fmaf(by,  by,  bxx));
        const float dB2 = fsqrt_approx(fmaf(by2, by2, bxx));
        a1A += fexp2_approx(-dA1);
        a2A += fexp2_approx(-dA2);
        a1B += fexp2_approx(-dB1);
        a2B += fexp2_approx(-dB2);
    }

    // ---- exchange partials within the pair, combine, finalize 32 px per warp ----
    partial[w][lane]      = a1A + a1B;       // pixel id = lane      (row block 0)
    partial[w][lane + 32] = a2A + a2B;       // pixel id = lane + 32 (row block 1)
    asm volatile("bar.sync %0, %1;" :: "r"(pair + 1), "r"(64) : "memory");

    const float acc = partial[2 * pair][q] + partial[2 * pair + 1][q];
    const float md  = flog2_approx(acc) * (-0.69314718f / 256.0f);
    const float z   = (0.04f - md) * (200.0f * 1.44269504f);
    out[fp] = frcp_approx(1.0f + fexp2_approx(z));
}

extern "C" void kernel_launch(void* const* d_in, const int* in_sizes, int n_in,
                              void* d_out, int out_size) {
    const float* cp = (const float*)d_in[0];   // control_points [8,4,2]
    float* out = (float*)d_out;
    glyph_kernel<<<2048, NT>>>(cp, out);       // 2048 CTAs x 2 pair-tiles = 4096 tiles
}